// round 1
// baseline (speedup 1.0000x reference)
#include <cuda_runtime.h>
#include <mma.h>
#include <math.h>

using namespace nvcuda;

// Problem constants
#define BB 2
#define SS 2048
#define HH 16
#define DD 64
#define DIM 1024
#define MROWS (BB*SS)          // 4096

// Scratch (device globals — no allocations allowed)
__device__ float g_Q[BB*HH*SS*DD];   // (B,H,S,D)
__device__ float g_K[BB*HH*SS*DD];
__device__ float g_V[BB*HH*SS*DD];
__device__ float g_O[MROWS*DIM];     // (B,S,H*D)

#define ATT_SMEM ((4*64*72 + 64*64 + 128) * 4)

template<class F>
__device__ __forceinline__ void frag_to_tf32(F& f) {
#pragma unroll
    for (int t = 0; t < f.num_elements; t++) f.x[t] = wmma::__float_to_tf32(f.x[t]);
}

// ---------------------------------------------------------------------------
// QKV projection: C(4096x1024) = x(4096x1024) @ W(1024x1024), scattered into
// (B,H,S,D) layout. N-tile of 64 == D, so each block column is exactly one head.
// ---------------------------------------------------------------------------
__global__ __launch_bounds__(128) void qkv_kernel(
    const float* __restrict__ x, const float* __restrict__ Wq,
    const float* __restrict__ Wk, const float* __restrict__ Wv)
{
    __shared__ float Xs[64*40];   // 64 rows x 32 cols, ld 40
    __shared__ float Ws[32*72];   // 32 rows x 64 cols, ld 72

    const float* W; float* out;
    if (blockIdx.z == 0)      { W = Wq; out = g_Q; }
    else if (blockIdx.z == 1) { W = Wk; out = g_K; }
    else                      { W = Wv; out = g_V; }

    const int tid = threadIdx.x, wid = tid >> 5, wm = wid >> 1, wn = wid & 1;
    const int m0 = blockIdx.y * 64, n0 = blockIdx.x * 64;

    wmma::fragment<wmma::accumulator,16,16,8,float> acc[2][2];
#pragma unroll
    for (int i = 0; i < 2; i++)
#pragma unroll
        for (int j = 0; j < 2; j++) wmma::fill_fragment(acc[i][j], 0.f);

    for (int k0 = 0; k0 < DIM; k0 += 32) {
#pragma unroll
        for (int i = tid; i < 512; i += 128) {            // X tile: 64x32
            int r = i >> 3, c = (i & 7) << 2;
            *(float4*)(Xs + r*40 + c) = *(const float4*)(x + (size_t)(m0 + r)*DIM + k0 + c);
        }
#pragma unroll
        for (int i = tid; i < 512; i += 128) {            // W tile: 32x64
            int r = i >> 4, c = (i & 15) << 2;
            *(float4*)(Ws + r*72 + c) = *(const float4*)(W + (size_t)(k0 + r)*DIM + n0 + c);
        }
        __syncthreads();
#pragma unroll
        for (int kk = 0; kk < 4; kk++) {
            wmma::fragment<wmma::matrix_a,16,16,8,wmma::precision::tf32,wmma::row_major> a[2];
            wmma::fragment<wmma::matrix_b,16,16,8,wmma::precision::tf32,wmma::row_major> bf[2];
#pragma unroll
            for (int i = 0; i < 2; i++) {
                wmma::load_matrix_sync(a[i], Xs + (wm*32 + i*16)*40 + kk*8, 40);
                frag_to_tf32(a[i]);
            }
#pragma unroll
            for (int j = 0; j < 2; j++) {
                wmma::load_matrix_sync(bf[j], Ws + (kk*8)*72 + wn*32 + j*16, 72);
                frag_to_tf32(bf[j]);
            }
#pragma unroll
            for (int i = 0; i < 2; i++)
#pragma unroll
                for (int j = 0; j < 2; j++)
                    wmma::mma_sync(acc[i][j], a[i], bf[j], acc[i][j]);
        }
        __syncthreads();
    }

    // Store into (B,H,S,D): block col = head h, rows = (b, s0..s0+63)
    const int bb = m0 >> 11, s0 = m0 & 2047, h = blockIdx.x;
    float* base = out + ((size_t)((bb << 4) + h) * SS + s0) * DD;
#pragma unroll
    for (int i = 0; i < 2; i++)
#pragma unroll
        for (int j = 0; j < 2; j++)
            wmma::store_matrix_sync(base + (wm*32 + i*16)*DD + (wn*32 + j*16),
                                    acc[i][j], DD, wmma::mem_row_major);
}

// ---------------------------------------------------------------------------
// Attention: per (b,h,qblock). Replicates reference recurrence exactly:
//   m_new = max(m, max_blk(s)); p = exp(s - m_new); alpha = exp(m - m_new)
//   l_new = alpha*l + sum(p);   o = (alpha*o + p@v) / l_new    (every iter!)
// ---------------------------------------------------------------------------
__global__ __launch_bounds__(128) void attn_kernel()
{
    extern __shared__ float smf[];
    float* Qs = smf;               // 64 x 72
    float* Ks = Qs + 64*72;        // 64 x 72
    float* Vs = Ks + 64*72;        // 64 x 72
    float* Ss = Vs + 64*72;        // 64 x 72 (scores / P / PV staging)
    float* Os = Ss + 64*72;        // 64 x 64 running output
    float* alpha_s = Os + 64*64;   // 64
    float* inv_s   = alpha_s + 64; // 64

    const int tid = threadIdx.x, wid = tid >> 5, lane = tid & 31;
    const int qb = blockIdx.x, h = blockIdx.y, b = blockIdx.z;
    const float scale = 0.125f;    // D^-0.5

    const float* Qg  = g_Q + ((size_t)((b << 4) + h) * SS + qb * 64) * DD;
    const float* Kg0 = g_K + (size_t)((b << 4) + h) * SS * DD;
    const float* Vg0 = g_V + (size_t)((b << 4) + h) * SS * DD;

#pragma unroll
    for (int i = tid; i < 1024; i += 128) {       // load Q tile
        int r = i >> 4, c = (i & 15) << 2;
        *(float4*)(Qs + r*72 + c) = *(const float4*)(Qg + r*DD + c);
    }
#pragma unroll
    for (int i = tid; i < 4096; i += 128) Os[i] = 0.f;

    const int row   = wid * 16 + (lane >> 1);     // softmax: 2 lanes per row
    const int cbase = (lane & 1) * 32;
    float mrun = -INFINITY, lrun = 0.f;

    for (int j = 0; j < 32; j++) {
        const float* Kg = Kg0 + j * 4096;
        const float* Vg = Vg0 + j * 4096;
#pragma unroll
        for (int i = tid; i < 1024; i += 128) {   // load K,V tiles
            int r = i >> 4, c = (i & 15) << 2;
            *(float4*)(Ks + r*72 + c) = *(const float4*)(Kg + r*DD + c);
            *(float4*)(Vs + r*72 + c) = *(const float4*)(Vg + r*DD + c);
        }
        __syncthreads();

        // S = scale * Q @ K^T — warp owns rows [wid*16, wid*16+16)
        {
            wmma::fragment<wmma::accumulator,16,16,8,float> sacc[4];
#pragma unroll
            for (int n = 0; n < 4; n++) wmma::fill_fragment(sacc[n], 0.f);
#pragma unroll
            for (int kk = 0; kk < 8; kk++) {
                wmma::fragment<wmma::matrix_a,16,16,8,wmma::precision::tf32,wmma::row_major> af;
                wmma::load_matrix_sync(af, Qs + (wid*16)*72 + kk*8, 72);
                frag_to_tf32(af);
#pragma unroll
                for (int n = 0; n < 4; n++) {
                    wmma::fragment<wmma::matrix_b,16,16,8,wmma::precision::tf32,wmma::col_major> bf;
                    wmma::load_matrix_sync(bf, Ks + (n*16)*72 + kk*8, 72);
                    frag_to_tf32(bf);
                    wmma::mma_sync(sacc[n], af, bf, sacc[n]);
                }
            }
#pragma unroll
            for (int n = 0; n < 4; n++) {
#pragma unroll
                for (int t = 0; t < sacc[n].num_elements; t++) sacc[n].x[t] *= scale;
                wmma::store_matrix_sync(Ss + (wid*16)*72 + n*16, sacc[n], 72, wmma::mem_row_major);
            }
        }
        __syncwarp();

        // Online softmax, warp-local rows (2 lanes per row, 32 cols each)
        {
            float* srow = Ss + row*72 + cbase;
            float mx = -INFINITY;
#pragma unroll
            for (int c = 0; c < 32; c++) mx = fmaxf(mx, srow[c]);
            mx = fmaxf(mx, __shfl_xor_sync(0xffffffffu, mx, 1));
            float mnew = fmaxf(mrun, mx);
            float sum = 0.f;
#pragma unroll
            for (int c = 0; c < 32; c++) {
                float p = __expf(srow[c] - mnew);
                srow[c] = p;
                sum += p;
            }
            sum += __shfl_xor_sync(0xffffffffu, sum, 1);
            float alpha = __expf(mrun - mnew);
            float lnew = alpha * lrun + sum;
            if ((lane & 1) == 0) { alpha_s[row] = alpha; inv_s[row] = 1.f / lnew; }
            mrun = mnew; lrun = lnew;
        }
        __syncwarp();

        // PV = P @ V, result staged back into Ss (warp-local rows)
        {
            wmma::fragment<wmma::accumulator,16,16,8,float> pacc[4];
#pragma unroll
            for (int n = 0; n < 4; n++) wmma::fill_fragment(pacc[n], 0.f);
#pragma unroll
            for (int kk = 0; kk < 8; kk++) {
                wmma::fragment<wmma::matrix_a,16,16,8,wmma::precision::tf32,wmma::row_major> af;
                wmma::load_matrix_sync(af, Ss + (wid*16)*72 + kk*8, 72);
                frag_to_tf32(af);
#pragma unroll
                for (int n = 0; n < 4; n++) {
                    wmma::fragment<wmma::matrix_b,16,16,8,wmma::precision::tf32,wmma::row_major> bf;
                    wmma::load_matrix_sync(bf, Vs + (kk*8)*72 + n*16, 72);
                    frag_to_tf32(bf);
                    wmma::mma_sync(pacc[n], af, bf, pacc[n]);
                }
            }
#pragma unroll
            for (int n = 0; n < 4; n++)
                wmma::store_matrix_sync(Ss + (wid*16)*72 + n*16, pacc[n], 72, wmma::mem_row_major);
        }
        __syncthreads();

        // o = (alpha*o + PV) / l_new
#pragma unroll
        for (int i = tid; i < 4096; i += 128) {
            int r = i >> 6, c = i & 63;
            Os[i] = (alpha_s[r] * Os[i] + Ss[r*72 + c]) * inv_s[r];
        }
        __syncthreads();
    }

    // Write to (B, S, H*D) layout for the output projection
    float* Og = g_O + ((size_t)(b * SS + qb * 64)) * DIM + h * DD;
#pragma unroll
    for (int i = tid; i < 1024; i += 128) {
        int r = i >> 4, c = (i & 15) << 2;
        *(float4*)(Og + (size_t)r*DIM + c) = *(const float4*)(Os + r*DD + c);
    }
}

// ---------------------------------------------------------------------------
// Output projection: d_out(4096x1024) = g_O(4096x1024) @ Wo(1024x1024)
// ---------------------------------------------------------------------------
__global__ __launch_bounds__(128) void oproj_kernel(
    const float* __restrict__ Wo, float* __restrict__ C)
{
    __shared__ float Xs[64*40];
    __shared__ float Ws[32*72];

    const int tid = threadIdx.x, wid = tid >> 5, wm = wid >> 1, wn = wid & 1;
    const int m0 = blockIdx.y * 64, n0 = blockIdx.x * 64;

    wmma::fragment<wmma::accumulator,16,16,8,float> acc[2][2];
#pragma unroll
    for (int i = 0; i < 2; i++)
#pragma unroll
        for (int j = 0; j < 2; j++) wmma::fill_fragment(acc[i][j], 0.f);

    for (int k0 = 0; k0 < DIM; k0 += 32) {
#pragma unroll
        for (int i = tid; i < 512; i += 128) {
            int r = i >> 3, c = (i & 7) << 2;
            *(float4*)(Xs + r*40 + c) = *(const float4*)(g_O + (size_t)(m0 + r)*DIM + k0 + c);
        }
#pragma unroll
        for (int i = tid; i < 512; i += 128) {
            int r = i >> 4, c = (i & 15) << 2;
            *(float4*)(Ws + r*72 + c) = *(const float4*)(Wo + (size_t)(k0 + r)*DIM + n0 + c);
        }
        __syncthreads();
#pragma unroll
        for (int kk = 0; kk < 4; kk++) {
            wmma::fragment<wmma::matrix_a,16,16,8,wmma::precision::tf32,wmma::row_major> a[2];
            wmma::fragment<wmma::matrix_b,16,16,8,wmma::precision::tf32,wmma::row_major> bf[2];
#pragma unroll
            for (int i = 0; i < 2; i++) {
                wmma::load_matrix_sync(a[i], Xs + (wm*32 + i*16)*40 + kk*8, 40);
                frag_to_tf32(a[i]);
            }
#pragma unroll
            for (int j = 0; j < 2; j++) {
                wmma::load_matrix_sync(bf[j], Ws + (kk*8)*72 + wn*32 + j*16, 72);
                frag_to_tf32(bf[j]);
            }
#pragma unroll
            for (int i = 0; i < 2; i++)
#pragma unroll
                for (int j = 0; j < 2; j++)
                    wmma::mma_sync(acc[i][j], a[i], bf[j], acc[i][j]);
        }
        __syncthreads();
    }

    float* base = C + (size_t)m0 * DIM + n0;
#pragma unroll
    for (int i = 0; i < 2; i++)
#pragma unroll
        for (int j = 0; j < 2; j++)
            wmma::store_matrix_sync(base + (size_t)(wm*32 + i*16)*DIM + (wn*32 + j*16),
                                    acc[i][j], DIM, wmma::mem_row_major);
}

// ---------------------------------------------------------------------------
extern "C" void kernel_launch(void* const* d_in, const int* in_sizes, int n_in,
                              void* d_out, int out_size)
{
    const float* x  = (const float*)d_in[0];
    const float* Wq = (const float*)d_in[1];
    const float* Wk = (const float*)d_in[2];
    const float* Wv = (const float*)d_in[3];
    const float* Wo = (const float*)d_in[4];

    cudaFuncSetAttribute(attn_kernel, cudaFuncAttributeMaxDynamicSharedMemorySize, ATT_SMEM);

    qkv_kernel<<<dim3(16, 64, 3), 128>>>(x, Wq, Wk, Wv);
    attn_kernel<<<dim3(32, 16, 2), 128, ATT_SMEM>>>();
    oproj_kernel<<<dim3(16, 64), 128>>>(Wo, (float*)d_out);
}